// round 8
// baseline (speedup 1.0000x reference)
#include <cuda_runtime.h>

// SSIM loss, fully fused one-kernel version, 4-plane formulation.
// img1, img2: [32,3,512,512] fp32. Output: scalar fp32 = 1 - mean(ssim_map).
//
// Planes: conv(x), conv(y), conv(x^2+y^2), conv(x*y) (x²,y² folded pre-conv).
// Per block: one (plane, 88-row band), 512 threads. Vertical 11-tap conv via
// 11-phase register accumulator ring (1 col/thread), 8-row groups into
// double-buffered smem; horizontal 11-tap conv + SSIM at 8 px/thread (LDS.128),
// epilogue folded incrementally to bound register pressure.

#define HW       512
#define NPLANES  96
#define BAND     88
#define NBANDS   6
#define NBLK     (NBANDS * NPLANES)   // 576
#define VB       528
#define VB4      (VB / 4)             // 132
#define GROWS    8
#define SMEM_DYN (2 * 4 * GROWS * VB4 * 16)   // 135168 bytes

namespace {
constexpr double G_[6] = {0.0038659201595884, 0.0285655007845504,
                          0.1353352832366127, 0.4111122905071874,
                          0.8007374029168081, 1.0};
constexpr double GSUM = 2.0*(G_[0]+G_[1]+G_[2]+G_[3]+G_[4]) + 1.0;
constexpr float gwf(int j){ return (float)(G_[j < 6 ? j : 10 - j] / GSUM); }
}

__device__ constexpr float GW[11] = {
    gwf(0), gwf(1), gwf(2), gwf(3), gwf(4), gwf(5),
    gwf(6), gwf(7), gwf(8), gwf(9), gwf(10)};

__device__ float    g_part[NBLK];
__device__ unsigned g_count = 0;

// Deposit j of ingested row (ring phase PH) -> slot (PH+j+6)%11, belonging to
// output row o = r + j - 5. JMIN masks prologue deposits (only o >= o0).
// j == 10 is always the FIRST write to its slot since that slot's emit
// (validated R6/R7: identical rel_err) -> plain MUL, no ring init anywhere.
// Planes: 0 = x, 1 = y, 2 = x^2 + y^2, 3 = x*y.
template<int PH, int JMIN>
__device__ __forceinline__ void ingest(float (&A)[4][11], float v1, float v2)
{
    const float q2  = v1 * v1;
    const float q23 = fmaf(v2, v2, q2);
    const float q4  = v1 * v2;
#pragma unroll
    for (int j = JMIN; j < 11; ++j) {
        const int   s = (PH + j + 6) % 11;
        const float w = GW[j];
        if (j == 10) {
            A[0][s] = w * v1;
            A[1][s] = w * v2;
            A[2][s] = w * q23;
            A[3][s] = w * q4;
        } else {
            A[0][s] = fmaf(w, v1,  A[0][s]);
            A[1][s] = fmaf(w, v2,  A[1][s]);
            A[2][s] = fmaf(w, q23, A[2][s]);
            A[3][s] = fmaf(w, q4,  A[3][s]);
        }
    }
}

// 20 consecutive floats of one staging plane row (5 x LDS.128).
__device__ __forceinline__ void hload20(const float4* q, float (&v)[20])
{
#pragma unroll
    for (int t = 0; t < 5; ++t) {
        const float4 u = q[t];
        v[4*t] = u.x; v[4*t+1] = u.y; v[4*t+2] = u.z; v[4*t+3] = u.w;
    }
}

// 11-tap horizontal conv, 8 adjacent outputs.
__device__ __forceinline__ void hconv8(const float (&v)[20], float (&r)[8])
{
#pragma unroll
    for (int i = 0; i < 8; ++i) {
        float s = GW[0] * v[i];
#pragma unroll
        for (int k = 1; k < 11; ++k) s = fmaf(GW[k], v[i + k], s);
        r[i] = s;
    }
}

__global__ __launch_bounds__(512, 1)
void ssim_main(const float* __restrict__ img1, const float* __restrict__ img2,
               float* __restrict__ out)
{
    extern __shared__ float4 dynbuf[];   // [2][4][GROWS][VB4]
#define VBUF(B, P, S) ((float*)(dynbuf + (((B)*4 + (P))*GROWS + (S)) * VB4))

    const int c     = threadIdx.x;
    const int band  = blockIdx.x;
    const int plane = blockIdx.y;
    const int o0    = band * BAND;
    const float* __restrict__ p1 = img1 + (size_t)plane * HW * HW;
    const float* __restrict__ p2 = img2 + (size_t)plane * HW * HW;

    __shared__ float  red[16];
    __shared__ double sd[512];
    __shared__ int    amLast;

    // one-time zero of column borders (emits only touch [5,516])
#pragma unroll
    for (int b = 0; b < 2; ++b)
#pragma unroll
        for (int p = 0; p < 4; ++p)
#pragma unroll
            for (int s = 0; s < GROWS; ++s) {
                float* bb = VBUF(b, p, s);
                if (c < 5)    bb[c] = 0.f;
                if (c >= 501) bb[c + 16] = 0.f;   // 517..527
            }

    float acc[4][11];   // no init: first touch of every slot is the j==10 MUL

    __syncthreads();

    // ingest rows for group G: rows o0+8G+5 .. o0+8G+12
    float nv1[GROWS], nv2[GROWS];
#define LOADS(G) {                                                           \
        _Pragma("unroll")                                                    \
        for (int i = 0; i < GROWS; ++i) {                                    \
            const int  r_  = o0 + 8 * (G) + 5 + i;                           \
            const bool ok_ = r_ < HW;                                        \
            nv1[i] = ok_ ? __ldg(&p1[(size_t)r_ * HW + c]) : 0.f;            \
            nv2[i] = ok_ ? __ldg(&p2[(size_t)r_ * HW + c]) : 0.f;            \
        } }

    // issue group-0 loads early; the prologue FMA chain hides their latency
    LOADS(0)

    // ── prologue: rows o0-5 .. o0+4, JMIN = 10-i masking ──
#define PROLOG(i) {                                                          \
        const int  r_  = o0 - 5 + (i);                                       \
        const bool ok_ = (unsigned)r_ < (unsigned)HW;                        \
        const float v1_ = ok_ ? __ldg(&p1[(size_t)r_ * HW + c]) : 0.f;       \
        const float v2_ = ok_ ? __ldg(&p2[(size_t)r_ * HW + c]) : 0.f;       \
        ingest<((i) + 6) % 11, 10 - (i)>(acc, v1_, v2_); }
    PROLOG(0) PROLOG(1) PROLOG(2) PROLOG(3) PROLOG(4)
    PROLOG(5) PROLOG(6) PROLOG(7) PROLOG(8) PROLOG(9)
#undef PROLOG

    // ingest + emit sub-row i of group G: step T = 8G+i, row o0+T+5,
    // ring phase (T+5)%11, emit slot T%11, buffer G&1, staging sub-row i
#define ING(G, i) {                                                          \
        ingest<((8 * (G) + (i)) + 5) % 11, 0>(acc, nv1[(i)], nv2[(i)]);      \
        _Pragma("unroll")                                                    \
        for (int p = 0; p < 4; ++p)                                          \
            VBUF((G) & 1, p, (i))[c + 5] = acc[p][(8 * (G) + (i)) % 11]; }

#define ING8(G) ING(G,0) ING(G,1) ING(G,2) ING(G,3) \
                ING(G,4) ING(G,5) ING(G,6) ING(G,7)

    float lsum = 0.f;
    const int rr = c >> 6;            // horizontal: row within group (0..7)
    const int cq = c & 63;            // horizontal: 8-px segment index

    // horizontal conv + SSIM for group G out of buffer B, 8 px/thread.
    // Epilogue folded incrementally: planes x,y -> mu12,msum; plane x2+y2
    // collapses to den; plane xy finishes. Bounds register peak.
#define HSTEP(G, B) {                                                        \
        float v[20], m1[8], m2[8];                                           \
        hload20((const float4*)VBUF(B, 0, rr) + 2 * cq, v);                  \
        hconv8(v, m1);                                                       \
        hload20((const float4*)VBUF(B, 1, rr) + 2 * cq, v);                  \
        hconv8(v, m2);                                                       \
        float mu12[8], msum[8];                                              \
        _Pragma("unroll")                                                    \
        for (int i = 0; i < 8; ++i) {                                        \
            mu12[i] = m1[i] * m2[i];                                         \
            msum[i] = fmaf(m1[i], m1[i], m2[i] * m2[i]);                     \
        }                                                                    \
        hload20((const float4*)VBUF(B, 2, rr) + 2 * cq, v);                  \
        hconv8(v, m1);                    /* m1 = conv(x^2+y^2) */           \
        float den[8];                                                        \
        _Pragma("unroll")                                                    \
        for (int i = 0; i < 8; ++i)                                          \
            den[i] = (msum[i] + 1e-4f) * ((m1[i] - msum[i]) + 9e-4f);        \
        hload20((const float4*)VBUF(B, 3, rr) + 2 * cq, v);                  \
        hconv8(v, m2);                    /* m2 = conv(x*y) */               \
        const int o = o0 + 8 * (G) + rr;                                     \
        if (o < HW) {                                                        \
            _Pragma("unroll")                                                \
            for (int i = 0; i < 8; ++i) {                                    \
                const float Anum = 2.f * mu12[i] + 1e-4f;                    \
                const float Bnum = 2.f * (m2[i] - mu12[i]) + 9e-4f;          \
                lsum += __fdividef(Anum * Bnum, den[i]);                     \
            }                                                                \
        } }

    // group 0: ingest bank already loaded
    ING8(0)

#define GBODY(G) {                                                           \
        __syncthreads();                                                     \
        LOADS(G)                                                             \
        HSTEP((G) - 1, ((G) - 1) & 1)                                        \
        ING8(G) }
    GBODY(1) GBODY(2) GBODY(3) GBODY(4) GBODY(5)
    GBODY(6) GBODY(7) GBODY(8) GBODY(9) GBODY(10)
#undef GBODY

    __syncthreads();
    HSTEP(10, 0)

#undef HSTEP
#undef ING8
#undef ING
#undef LOADS
#undef VBUF

    // ── block reduction ──
    float v = lsum;
#pragma unroll
    for (int off = 16; off; off >>= 1)
        v += __shfl_xor_sync(0xFFFFFFFFu, v, off);
    if ((c & 31) == 0) red[c >> 5] = v;
    __syncthreads();

    if (c == 0) {
        float bs = 0.f;
#pragma unroll
        for (int w = 0; w < 16; ++w) bs += red[w];
        g_part[plane * NBANDS + band] = bs;
        __threadfence();
        const unsigned t = atomicAdd(&g_count, 1u);
        amLast = (t == NBLK - 1);
    }
    __syncthreads();

    if (amLast) {
        __threadfence();
        double s = 0.0;
        for (int i = c; i < NBLK; i += 512) s += (double)g_part[i];
        sd[c] = s;
        __syncthreads();
#pragma unroll
        for (int k = 256; k > 0; k >>= 1) {
            if (c < k) sd[c] += sd[c + k];
            __syncthreads();
        }
        if (c == 0) {
            out[0]  = (float)(1.0 - sd[0] / 25165824.0);  // 32*3*512*512
            g_count = 0;                                   // reset for replay
        }
    }
}

extern "C" void kernel_launch(void* const* d_in, const int* in_sizes, int n_in,
                              void* d_out, int out_size)
{
    (void)in_sizes; (void)n_in; (void)out_size;
    const float* img1 = (const float*)d_in[0];
    const float* img2 = (const float*)d_in[1];
    cudaFuncSetAttribute(ssim_main, cudaFuncAttributeMaxDynamicSharedMemorySize,
                         SMEM_DYN);
    dim3 grid(NBANDS, NPLANES);
    ssim_main<<<grid, 512, SMEM_DYN>>>(img1, img2, (float*)d_out);
}